// round 10
// baseline (speedup 1.0000x reference)
#include <cuda_runtime.h>

#define BB    8
#define LL    24
#define HPL   32
#define HID   10
#define PIX   4096
#define NCH   768      // N = L*HPL
#define C3    96
#define OC    64
#define NTILE 16       // pixel tiles of 256 (128 threads x 2 px)
#define NQ    4        // output quarter-groups (16 outputs each)

// output section offsets (elements)
#define OFF_LOGITS 0ULL
#define OFF_COEFF  50331648ULL
#define OFF_WA     100663296ULL
#define OFF_WB     125829120ULL
#define OFF_MIXED  150994944ULL

// scratch (no allocations allowed -> device globals)
__device__ float g_xmean[BB][2 * NCH];               // per-(b,channel) mean of x
__device__ float g_psum[2][BB][NTILE][HPL];          // per-tile partial sums of mixed

// ---------------- packed f32x2 helpers (Blackwell FFMA2) ----------------
__device__ __forceinline__ unsigned long long pack2(float v) {
    unsigned long long r;
    asm("mov.b64 %0, {%1, %1};" : "=l"(r) : "f"(v));
    return r;
}
__device__ __forceinline__ unsigned long long packf2(float lo, float hi) {
    unsigned long long r;
    asm("mov.b64 %0, {%1, %2};" : "=l"(r) : "f"(lo), "f"(hi));
    return r;
}
__device__ __forceinline__ unsigned long long ffma2(unsigned long long a, unsigned long long b, unsigned long long c) {
    unsigned long long d;
    asm("fma.rn.f32x2 %0, %1, %2, %3;" : "=l"(d) : "l"(a), "l"(b), "l"(c));
    return d;
}
__device__ __forceinline__ float2 unpack2(unsigned long long a) {
    float2 f;
    asm("mov.b64 {%0, %1}, %2;" : "=f"(f.x), "=f"(f.y) : "l"(a));
    return f;
}
__device__ __forceinline__ float sigmoidf_fast(float z) {
    return __fdividef(1.0f, 1.0f + __expf(-z));
}

// ---------------- channel means of x (all layers, upfront) ----------------
__global__ __launch_bounds__(256) void means_kernel(const float* __restrict__ x) {
    int ch = blockIdx.x;   // b*1536 + c
    const float4* p = reinterpret_cast<const float4*>(x + (size_t)ch * PIX);
    float s = 0.f;
    for (int i = threadIdx.x; i < PIX / 4; i += 256) {
        float4 v = p[i];
        s += (v.x + v.y) + (v.z + v.w);
    }
    #pragma unroll
    for (int o = 16; o; o >>= 1) s += __shfl_xor_sync(~0u, s, o);
    __shared__ float sb[8];
    if ((threadIdx.x & 31) == 0) sb[threadIdx.x >> 5] = s;
    __syncthreads();
    if (threadIdx.x == 0) {
        float t = 0.f;
        #pragma unroll
        for (int w = 0; w < 8; w++) t += sb[w];
        int b = ch / 1536, c = ch % 1536;
        g_xmean[b][c] = t * (1.0f / PIX);
    }
}

// ---------------- one recurrent layer (quarter of outputs, 2 px/thread) ---
__global__ __launch_bounds__(128, 4) void layer_kernel(
    const float* __restrict__ x,
    const float* __restrict__ W1, const float* __restrict__ b1,
    const float* __restrict__ W2, const float* __restrict__ b2,
    const float* __restrict__ Wc, const float* __restrict__ bc,
    float* __restrict__ out, int l)
{
    __shared__ __align__(16) float2 wc_s[C3][8];   // (Wc[2op][c], Wc[2op+1][c]) : 6 KB
    __shared__ float gc_s[C3];
    __shared__ float hm_s[HID];
    __shared__ float glc_s[16];
    __shared__ float red_s[4][8];

    const int tid   = threadIdx.x;
    const int b     = blockIdx.y;
    const int tile  = blockIdx.x;
    const int q     = blockIdx.z;
    const int qbase = q * 8;                        // first op-group owned (of 8)
    const int p2    = (tile * 128 + tid) * 2;       // first of 2 consecutive pixels

    // --- stage Wc[l] (16 rows) transposed + output-channel-paired ---
    const float* wcl = Wc + (size_t)l * OC * C3;
    for (int idx = tid; idx < 8 * C3; idx += 128) {
        int opl = idx / C3, c = idx % C3;           // coalesced over c
        int op = qbase + opl;
        wc_s[c][opl] = make_float2(wcl[(2 * op) * C3 + c], wcl[(2 * op + 1) * C3 + c]);
    }

    // --- gc (channel means of cat) ---
    const int rbuf = (l - 1) & 1;
    const int wbuf = l & 1;
    if (tid < C3) {
        float m;
        if (tid < 32)      m = g_xmean[b][l * HPL + tid];
        else if (tid < 64) m = g_xmean[b][NCH + l * HPL + (tid - 32)];
        else {
            if (l == 0) m = 0.f;
            else {
                float s = 0.f;
                #pragma unroll
                for (int t = 0; t < NTILE; t++) s += g_psum[rbuf][b][t][tid - 64];
                m = s * (1.0f / PIX);
            }
        }
        gc_s[tid] = m;
    }
    __syncthreads();

    // --- tiny MLP: hmid = silu(gc @ W1^T + b1) ---
    if (tid < HID) {
        const float* w1 = W1 + (size_t)l * HID * C3 + tid * C3;
        float z = b1[l * HID + tid];
        #pragma unroll
        for (int m = 0; m < C3; m++) z += gc_s[m] * w1[m];
        hm_s[tid] = z * sigmoidf_fast(z);
    }
    __syncthreads();

    // --- glc for this block's 16 outputs ---
    if (tid < 16) {
        int o = 2 * qbase + tid;
        const float* w2 = W2 + (size_t)l * OC * HID + o * HID;
        float z = b2[l * OC + o] + bc[l * OC + o];
        #pragma unroll
        for (int h = 0; h < HID; h++) z += hm_s[h] * w2[h];
        glc_s[tid] = z;
    }
    __syncthreads();

    // --- accumulators: [px][op-group] 8 f32x2 x 2 px, seeded with glc ---
    unsigned long long acc[2][8];
    #pragma unroll
    for (int opl = 0; opl < 8; opl++) {
        unsigned long long seed = packf2(glc_s[2 * opl], glc_s[2 * opl + 1]);
        acc[0][opl] = seed;
        acc[1][opl] = seed;
    }

    const float* xa = x + ((size_t)b * 1536 + l * HPL) * PIX + p2;
    const float* xb = xa + (size_t)NCH * PIX;
    const int lprev = (l == 0) ? 0 : (l - 1);       // avoid OOB pointer math at l=0
    const float* pv = out + OFF_MIXED + ((size_t)b * NCH + lprev * HPL) * PIX + p2;

    // --- main GEMM: 96 ch x 16 outputs x 2 px, doubly software-pipelined ---
    // LDG double-buffer at 8-channel group granularity (as R8) PLUS a
    // one-channel register double-buffer for the weight LDS fragments so the
    // 29-cycle LDS latency is covered by the previous channel's FFMA block.
    const int NG = (l == 0) ? 8 : 12;               // prev = 0 at l=0: skip seg 2
    unsigned long long vbuf[2][8];
    ulonglong2 wb[2][4];
    const ulonglong2* wrows = reinterpret_cast<const ulonglong2*>(&wc_s[0][0]);

    #pragma unroll
    for (int j = 0; j < 8; j++)
        vbuf[0][j] = *reinterpret_cast<const unsigned long long*>(xa + j * PIX);
    #pragma unroll
    for (int k = 0; k < 4; k++) wb[0][k] = wrows[k];   // weights for channel 0

    #pragma unroll
    for (int gi = 0; gi < 12; gi++) {
        if (gi >= NG) break;
        const int gcur = gi & 1, gnxt = gcur ^ 1;
        if (gi + 1 < NG) {
            #pragma unroll
            for (int j = 0; j < 8; j++) {
                const int c = (gi + 1) * 8 + j;     // compile-time per unrolled iter
                const float* s = (c < 32) ? (xa + c * PIX)
                               : (c < 64) ? (xb + (c - 32) * PIX)
                                          : (pv + (c - 64) * PIX);
                vbuf[gnxt][j] = *reinterpret_cast<const unsigned long long*>(s);
            }
        }
        #pragma unroll
        for (int j = 0; j < 8; j++) {
            const int c = gi * 8 + j;               // compile-time
            const int wcur = c & 1, wnxt = wcur ^ 1;
            // prefetch next channel's weight fragment (4 LDS.128)
            if (j < 7 || gi + 1 < NG) {
                #pragma unroll
                for (int k = 0; k < 4; k++)
                    wb[wnxt][k] = wrows[(c + 1) * 4 + k];
            }
            float2 v = unpack2(vbuf[gcur][j]);
            unsigned long long vp0 = pack2(v.x);
            unsigned long long vp1 = pack2(v.y);
            #pragma unroll
            for (int qq = 0; qq < 4; qq++) {
                ulonglong2 ww = wb[wcur][qq];
                acc[0][2*qq]   = ffma2(vp0, ww.x, acc[0][2*qq]);
                acc[0][2*qq+1] = ffma2(vp0, ww.y, acc[0][2*qq+1]);
                acc[1][2*qq]   = ffma2(vp1, ww.x, acc[1][2*qq]);
                acc[1][2*qq+1] = ffma2(vp1, ww.y, acc[1][2*qq+1]);
            }
        }
    }

    // --- batched reload of mix inputs (L1/L2-hot: same block just read them) ---
    float2 va8[8], vb8[8];
    #pragma unroll
    for (int opl = 0; opl < 8; opl++) {
        const int m0 = 3 * (qbase + opl);
        const int m1 = m0 + 1;
        const float* pa = (m0 < 32) ? (xa + m0 * PIX)
                        : (m0 < 64) ? (xb + (m0 - 32) * PIX)
                                    : (pv + (m0 - 64) * PIX);
        const float* pb = (m1 < 32) ? (xa + m1 * PIX)
                        : (m1 < 64) ? (xb + (m1 - 32) * PIX)
                                    : (pv + (m1 - 64) * PIX);
        va8[opl] = (l == 0 && m0 >= 64) ? make_float2(0.f, 0.f)
                                        : *reinterpret_cast<const float2*>(pa);
        vb8[opl] = (l == 0 && m1 >= 64) ? make_float2(0.f, 0.f)
                                        : *reinterpret_cast<const float2*>(pb);
    }

    // --- epilogue: float2 stores for logits/coeff/wa/wb/mixed + partials ---
    const int lane = tid & 31;
    const int wrp  = tid >> 5;
    const size_t base_bl = ((size_t)b * LL + l) * HPL;
    float mysum = 0.f;

    #pragma unroll
    for (int opl = 0; opl < 8; opl++) {
        const int op = qbase + opl;
        float2 s0 = unpack2(acc[0][opl]);
        float2 s1 = unpack2(acc[1][opl]);
        float2 sx = make_float2(s0.x, s1.x);        // logit A for px0, px1
        float2 sy = make_float2(s0.y, s1.y);        // logit B for px0, px1

        size_t ci = base_bl + op;
        size_t li = ci * 2 * PIX + p2;
        *reinterpret_cast<float2*>(out + OFF_LOGITS + li)       = sx;
        *reinterpret_cast<float2*>(out + OFF_LOGITS + li + PIX) = sy;

        float2 wbv, wav;
        wbv.x = sigmoidf_fast(sy.x - sx.x);
        wbv.y = sigmoidf_fast(sy.y - sx.y);
        wav = make_float2(1.f - wbv.x, 1.f - wbv.y);

        *reinterpret_cast<float2*>(out + OFF_COEFF + li)       = wav;
        *reinterpret_cast<float2*>(out + OFF_COEFF + li + PIX) = wbv;

        size_t si = ci * PIX + p2;
        *reinterpret_cast<float2*>(out + OFF_WA + si) = wav;
        *reinterpret_cast<float2*>(out + OFF_WB + si) = wbv;

        float2 va = va8[opl], vb = vb8[opl];
        float2 mix;
        mix.x = va.x + wbv.x * (vb.x - va.x);
        mix.y = va.y + wbv.y * (vb.y - va.y);
        *reinterpret_cast<float2*>(out + OFF_MIXED + si) = mix;

        // reduce mixed over this thread's 2 px, then across the warp
        float r = mix.x + mix.y;
        #pragma unroll
        for (int o = 16; o; o >>= 1) r += __shfl_xor_sync(~0u, r, o);
        if (lane == opl) mysum = r;
    }

    if (lane < 8) red_s[wrp][lane] = mysum;
    __syncthreads();
    if (tid < 8) {
        float t = red_s[0][tid] + red_s[1][tid] + red_s[2][tid] + red_s[3][tid];
        g_psum[wbuf][b][tile][qbase + tid] = t;   // each op written by exactly one block
    }
}

// ---------------- launch ----------------
extern "C" void kernel_launch(void* const* d_in, const int* in_sizes, int n_in,
                              void* d_out, int out_size) {
    const float* x  = (const float*)d_in[0];
    const float* W1 = (const float*)d_in[1];
    const float* b1 = (const float*)d_in[2];
    const float* W2 = (const float*)d_in[3];
    const float* b2 = (const float*)d_in[4];
    const float* Wc = (const float*)d_in[5];
    const float* bc = (const float*)d_in[6];
    float* out = (float*)d_out;

    means_kernel<<<BB * 2 * NCH, 256>>>(x);
    for (int l = 0; l < LL; l++)
        layer_kernel<<<dim3(NTILE, BB, NQ), 128>>>(x, W1, b1, W2, b2, Wc, bc, out, l);
}

// round 13
// speedup vs baseline: 1.5943x; 1.5943x over previous
#include <cuda_runtime.h>

#define BB    8
#define LL    24
#define HPL   32
#define HID   10
#define PIX   4096
#define NCH   768      // N = L*HPL
#define C3    96
#define OC    64
#define NTILE 8        // pixel tiles of 512 (128 threads x 4 px)
#define NQ    8        // output octets (8 outputs = 4 op-pairs per block)

// output section offsets (elements)
#define OFF_LOGITS 0ULL
#define OFF_COEFF  50331648ULL
#define OFF_WA     100663296ULL
#define OFF_WB     125829120ULL
#define OFF_MIXED  150994944ULL

// scratch (no allocations allowed -> device globals)
__device__ float g_xmean[BB][2 * NCH];               // per-(b,channel) mean of x
__device__ float g_psum[2][BB][NTILE][HPL];          // per-tile partial sums of mixed

// ---------------- packed f32x2 helpers (Blackwell FFMA2) ----------------
__device__ __forceinline__ unsigned long long pack2(float v) {
    unsigned long long r;
    asm("mov.b64 %0, {%1, %1};" : "=l"(r) : "f"(v));
    return r;
}
__device__ __forceinline__ unsigned long long packf2(float lo, float hi) {
    unsigned long long r;
    asm("mov.b64 %0, {%1, %2};" : "=l"(r) : "f"(lo), "f"(hi));
    return r;
}
__device__ __forceinline__ unsigned long long ffma2(unsigned long long a, unsigned long long b, unsigned long long c) {
    unsigned long long d;
    asm("fma.rn.f32x2 %0, %1, %2, %3;" : "=l"(d) : "l"(a), "l"(b), "l"(c));
    return d;
}
__device__ __forceinline__ float2 unpack2(unsigned long long a) {
    float2 f;
    asm("mov.b64 {%0, %1}, %2;" : "=f"(f.x), "=f"(f.y) : "l"(a));
    return f;
}
__device__ __forceinline__ float sigmoidf_fast(float z) {
    return __fdividef(1.0f, 1.0f + __expf(-z));
}

// ---------------- channel means of x (all layers, upfront) ----------------
__global__ __launch_bounds__(256) void means_kernel(const float* __restrict__ x) {
    int ch = blockIdx.x;   // b*1536 + c
    const float4* p = reinterpret_cast<const float4*>(x + (size_t)ch * PIX);
    float s = 0.f;
    for (int i = threadIdx.x; i < PIX / 4; i += 256) {
        float4 v = p[i];
        s += (v.x + v.y) + (v.z + v.w);
    }
    #pragma unroll
    for (int o = 16; o; o >>= 1) s += __shfl_xor_sync(~0u, s, o);
    __shared__ float sb[8];
    if ((threadIdx.x & 31) == 0) sb[threadIdx.x >> 5] = s;
    __syncthreads();
    if (threadIdx.x == 0) {
        float t = 0.f;
        #pragma unroll
        for (int w = 0; w < 8; w++) t += sb[w];
        int b = ch / 1536, c = ch % 1536;
        g_xmean[b][c] = t * (1.0f / PIX);
    }
}

// ------- one recurrent layer (octet of outputs, 4 px/thread, out-paired) --
__global__ __launch_bounds__(128, 4) void layer_kernel(
    const float* __restrict__ x,
    const float* __restrict__ W1, const float* __restrict__ b1,
    const float* __restrict__ W2, const float* __restrict__ b2,
    const float* __restrict__ Wc, const float* __restrict__ bc,
    float* __restrict__ out, int l)
{
    __shared__ __align__(16) float2 wc_s[C3][4];   // (Wc[2op][c], Wc[2op+1][c]) : 3 KB
    __shared__ float gc_s[C3];
    __shared__ float hm_s[HID];
    __shared__ float glc_s[8];
    __shared__ float red_s[4][4];

    const int tid   = threadIdx.x;
    const int b     = blockIdx.y;
    const int tile  = blockIdx.x;
    const int q     = blockIdx.z;                   // output octet (8 outputs)
    const int pbase = q * 4;                        // first op-pair owned (of 4)
    const int p4    = (tile * 128 + tid) * 4;       // first of 4 consecutive pixels

    // --- stage Wc[l] (8 rows) transposed + output-channel-paired ---
    const float* wcl = Wc + (size_t)l * OC * C3;
    for (int idx = tid; idx < 4 * C3; idx += 128) {
        int opl = idx / C3, c = idx % C3;           // coalesced over c
        int op = pbase + opl;
        wc_s[c][opl] = make_float2(wcl[(2 * op) * C3 + c], wcl[(2 * op + 1) * C3 + c]);
    }

    // --- gc (channel means of cat) ---
    const int rbuf = (l - 1) & 1;
    const int wbuf = l & 1;
    if (tid < C3) {
        float m;
        if (tid < 32)      m = g_xmean[b][l * HPL + tid];
        else if (tid < 64) m = g_xmean[b][NCH + l * HPL + (tid - 32)];
        else {
            if (l == 0) m = 0.f;
            else {
                float s = 0.f;
                #pragma unroll
                for (int t = 0; t < NTILE; t++) s += g_psum[rbuf][b][t][tid - 64];
                m = s * (1.0f / PIX);
            }
        }
        gc_s[tid] = m;
    }
    __syncthreads();

    // --- tiny MLP: hmid = silu(gc @ W1^T + b1) ---
    if (tid < HID) {
        const float* w1 = W1 + (size_t)l * HID * C3 + tid * C3;
        float z = b1[l * HID + tid];
        #pragma unroll
        for (int m = 0; m < C3; m++) z += gc_s[m] * w1[m];
        hm_s[tid] = z * sigmoidf_fast(z);
    }
    __syncthreads();

    // --- glc for this block's 8 outputs ---
    if (tid < 8) {
        int o = 2 * pbase + tid;
        const float* w2 = W2 + (size_t)l * OC * HID + o * HID;
        float z = b2[l * OC + o] + bc[l * OC + o];
        #pragma unroll
        for (int h = 0; h < HID; h++) z += hm_s[h] * w2[h];
        glc_s[tid] = z;
    }
    __syncthreads();

    // --- accumulators: acc[px][op-pair] = (out_2op, out_2op+1) @ px ---
    unsigned long long acc[4][4];                   // 16 u64 = 32 regs
    #pragma unroll
    for (int opl = 0; opl < 4; opl++) {
        unsigned long long seed = packf2(glc_s[2 * opl], glc_s[2 * opl + 1]);
        #pragma unroll
        for (int px = 0; px < 4; px++) acc[px][opl] = seed;
    }

    const float* xa = x + ((size_t)b * 1536 + l * HPL) * PIX + p4;
    const float* xb = xa + (size_t)NCH * PIX;
    const int lprev = (l == 0) ? 0 : (l - 1);
    const float* pv = out + OFF_MIXED + ((size_t)b * NCH + lprev * HPL) * PIX + p4;

    // --- main GEMM: 96 ch x 8 outputs x 4 px, software-pipelined ---
    // Per channel: 1 LDG.128 (prefetched) + 2 LDS.128 + 4 packs + 16 FFMA2.
    // Channel c's weights = 2 consecutive ulonglong2 at wrow[2c], wrow[2c+1].
    const int NG = (l == 0) ? 8 : 12;               // prev = 0 at l=0: skip seg 2
    float4 vbuf[2][8];
    #pragma unroll
    for (int j = 0; j < 8; j++)
        vbuf[0][j] = *reinterpret_cast<const float4*>(xa + j * PIX);

    const ulonglong2* wrows = reinterpret_cast<const ulonglong2*>(&wc_s[0][0]);

    #pragma unroll
    for (int gi = 0; gi < 12; gi++) {
        if (gi >= NG) break;
        const int cur = gi & 1, nxt = cur ^ 1;
        if (gi + 1 < NG) {
            #pragma unroll
            for (int j = 0; j < 8; j++) {
                const int c = (gi + 1) * 8 + j;     // compile-time per unrolled iter
                const float* s = (c < 32) ? (xa + c * PIX)
                               : (c < 64) ? (xb + (c - 32) * PIX)
                                          : (pv + (c - 64) * PIX);
                vbuf[nxt][j] = *reinterpret_cast<const float4*>(s);
            }
        }
        #pragma unroll
        for (int j = 0; j < 8; j++) {
            const int c = gi * 8 + j;               // compile-time channel index
            float4 v = vbuf[cur][j];
            unsigned long long vp0 = pack2(v.x);
            unsigned long long vp1 = pack2(v.y);
            unsigned long long vp2 = pack2(v.z);
            unsigned long long vp3 = pack2(v.w);
            ulonglong2 ww  = wrows[2 * c];          // op-pairs (0,1)
            ulonglong2 wwb = wrows[2 * c + 1];      // op-pairs (2,3)
            acc[0][0] = ffma2(vp0, ww.x,  acc[0][0]);
            acc[0][1] = ffma2(vp0, ww.y,  acc[0][1]);
            acc[0][2] = ffma2(vp0, wwb.x, acc[0][2]);
            acc[0][3] = ffma2(vp0, wwb.y, acc[0][3]);
            acc[1][0] = ffma2(vp1, ww.x,  acc[1][0]);
            acc[1][1] = ffma2(vp1, ww.y,  acc[1][1]);
            acc[1][2] = ffma2(vp1, wwb.x, acc[1][2]);
            acc[1][3] = ffma2(vp1, wwb.y, acc[1][3]);
            acc[2][0] = ffma2(vp2, ww.x,  acc[2][0]);
            acc[2][1] = ffma2(vp2, ww.y,  acc[2][1]);
            acc[2][2] = ffma2(vp2, wwb.x, acc[2][2]);
            acc[2][3] = ffma2(vp2, wwb.y, acc[2][3]);
            acc[3][0] = ffma2(vp3, ww.x,  acc[3][0]);
            acc[3][1] = ffma2(vp3, ww.y,  acc[3][1]);
            acc[3][2] = ffma2(vp3, wwb.x, acc[3][2]);
            acc[3][3] = ffma2(vp3, wwb.y, acc[3][3]);
        }
    }

    // --- batched reload of mix inputs (L1/L2-hot) for the 4 op-pairs ---
    float4 va4[4], vb4[4];
    #pragma unroll
    for (int opl = 0; opl < 4; opl++) {
        const int m0 = 3 * (pbase + opl);
        const int m1 = m0 + 1;
        const float* pa = (m0 < 32) ? (xa + m0 * PIX)
                        : (m0 < 64) ? (xb + (m0 - 32) * PIX)
                                    : (pv + (m0 - 64) * PIX);
        const float* pb = (m1 < 32) ? (xa + m1 * PIX)
                        : (m1 < 64) ? (xb + (m1 - 32) * PIX)
                                    : (pv + (m1 - 64) * PIX);
        va4[opl] = (l == 0 && m0 >= 64) ? make_float4(0.f, 0.f, 0.f, 0.f)
                                        : *reinterpret_cast<const float4*>(pa);
        vb4[opl] = (l == 0 && m1 >= 64) ? make_float4(0.f, 0.f, 0.f, 0.f)
                                        : *reinterpret_cast<const float4*>(pb);
    }

    // --- epilogue: float4 stores for logits/coeff/wa/wb/mixed + partials ---
    const int lane = tid & 31;
    const int wrp  = tid >> 5;
    const size_t base_bl = ((size_t)b * LL + l) * HPL;
    float mysum = 0.f;

    #pragma unroll
    for (int opl = 0; opl < 4; opl++) {
        const int op = pbase + opl;
        float2 s0 = unpack2(acc[0][opl]);
        float2 s1 = unpack2(acc[1][opl]);
        float2 s2 = unpack2(acc[2][opl]);
        float2 s3 = unpack2(acc[3][opl]);
        float4 sx = make_float4(s0.x, s1.x, s2.x, s3.x);   // logit A @ 4 px
        float4 sy = make_float4(s0.y, s1.y, s2.y, s3.y);   // logit B @ 4 px

        size_t ci = base_bl + op;
        size_t li = ci * 2 * PIX + p4;
        *reinterpret_cast<float4*>(out + OFF_LOGITS + li)       = sx;
        *reinterpret_cast<float4*>(out + OFF_LOGITS + li + PIX) = sy;

        float4 wbv, wav;
        wbv.x = sigmoidf_fast(sy.x - sx.x);
        wbv.y = sigmoidf_fast(sy.y - sx.y);
        wbv.z = sigmoidf_fast(sy.z - sx.z);
        wbv.w = sigmoidf_fast(sy.w - sx.w);
        wav = make_float4(1.f - wbv.x, 1.f - wbv.y, 1.f - wbv.z, 1.f - wbv.w);

        *reinterpret_cast<float4*>(out + OFF_COEFF + li)       = wav;
        *reinterpret_cast<float4*>(out + OFF_COEFF + li + PIX) = wbv;

        size_t si = ci * PIX + p4;
        *reinterpret_cast<float4*>(out + OFF_WA + si) = wav;
        *reinterpret_cast<float4*>(out + OFF_WB + si) = wbv;

        float4 va = va4[opl], vb = vb4[opl];
        float4 mix;
        mix.x = va.x + wbv.x * (vb.x - va.x);
        mix.y = va.y + wbv.y * (vb.y - va.y);
        mix.z = va.z + wbv.z * (vb.z - va.z);
        mix.w = va.w + wbv.w * (vb.w - va.w);
        *reinterpret_cast<float4*>(out + OFF_MIXED + si) = mix;

        // reduce mixed over this thread's 4 px, then across the warp
        float r = (mix.x + mix.y) + (mix.z + mix.w);
        #pragma unroll
        for (int o = 16; o; o >>= 1) r += __shfl_xor_sync(~0u, r, o);
        if (lane == opl) mysum = r;
    }

    if (lane < 4) red_s[wrp][lane] = mysum;
    __syncthreads();
    if (tid < 4) {
        float t = red_s[0][tid] + red_s[1][tid] + red_s[2][tid] + red_s[3][tid];
        g_psum[wbuf][b][tile][pbase + tid] = t;   // each op-pair written by one block
    }
}

// ---------------- launch ----------------
extern "C" void kernel_launch(void* const* d_in, const int* in_sizes, int n_in,
                              void* d_out, int out_size) {
    const float* x  = (const float*)d_in[0];
    const float* W1 = (const float*)d_in[1];
    const float* b1 = (const float*)d_in[2];
    const float* W2 = (const float*)d_in[3];
    const float* b2 = (const float*)d_in[4];
    const float* Wc = (const float*)d_in[5];
    const float* bc = (const float*)d_in[6];
    float* out = (float*)d_out;

    means_kernel<<<BB * 2 * NCH, 256>>>(x);
    for (int l = 0; l < LL; l++)
        layer_kernel<<<dim3(NTILE, BB, NQ), 128>>>(x, W1, b1, W2, b2, Wc, bc, out, l);
}